// round 5
// baseline (speedup 1.0000x reference)
#include <cuda_runtime.h>
#include <math_constants.h>
#include <cstdint>

// Problem constants (fixed by the reference)
#define BB 16
#define LL 2048
#define DD 512
#define SPLIT 32
#define STAGES 8    // 8 rows x 2KB = 16KB smem ring per CTA (single-wave occupancy)

// Scratch: partial maxima [which][batch][split][dim] = 2 MB (L2-resident)
__device__ float g_part[2][BB][SPLIT][DD];
// Per-batch arrival counter (zero at load; reset by the reducing CTA each replay).
__device__ unsigned int g_count[BB];

#define CP_ASYNC16(smem_u32, gptr) \
    asm volatile("cp.async.cg.shared.global [%0], [%1], 16;\n" :: "r"(smem_u32), "l"(gptr) : "memory")
#define CP_COMMIT() asm volatile("cp.async.commit_group;\n" ::: "memory")
#define CP_WAIT(n)  asm volatile("cp.async.wait_group %0;\n" :: "n"(n) : "memory")

// Fused kernel: masked split max (cp.async pipelined) + last-CTA-per-batch reduce & dot.
// grid = (SPLIT, B, 2), block = 128 (thread t owns dims 4t..4t+3).
// min 12 CTAs/SM -> regs <= ~42 -> whole grid fits in ONE wave (no straggler tail).
__global__ void __launch_bounds__(128, 12) fused_kernel(
    const float* __restrict__ x,
    const float* __restrict__ y,
    const int* __restrict__ mask_x,
    const int* __restrict__ mask_y,
    const float* __restrict__ W,
    const float* __restrict__ bias,
    float* __restrict__ out)
{
    __shared__ float buf[STAGES][DD];   // 16 KB ring; thread t owns [.][4t..4t+3]
    __shared__ int   warp_sums[4];
    __shared__ int   s_len;
    __shared__ int   s_last;
    __shared__ float red[4];

    const int split = blockIdx.x;
    const int b     = blockIdx.y;
    const int which = blockIdx.z;
    const int t     = threadIdx.x;   // 0..127

    const float* v = which ? y : x;
    const int*   m = which ? mask_y : mask_x;

    // ---- len[b] = L - sum(mask[b, :]) (block reduction over 2048 ints) ----
    int sum = 0;
    const int4* mrow = reinterpret_cast<const int4*>(m + (size_t)b * LL);
    #pragma unroll
    for (int i = t; i < LL / 4; i += 128) {
        int4 mv = mrow[i];
        sum += mv.x + mv.y + mv.z + mv.w;
    }
    #pragma unroll
    for (int o = 16; o; o >>= 1) sum += __shfl_down_sync(0xffffffffu, sum, o);

    if ((t & 31) == 0) warp_sums[t >> 5] = sum;
    __syncthreads();
    if (t == 0) s_len = LL - (warp_sums[0] + warp_sums[1] + warp_sums[2] + warp_sums[3]);
    __syncthreads();
    const int len = s_len;

    // ---- adaptive balanced chunking: every split gets ~len/SPLIT rows ----
    const int rpc = (len + SPLIT - 1) / SPLIT;
    const int s0  = split * rpc;
    const int s1  = min(s0 + rpc, len);
    const int n   = s1 - s0;

    const float* gbase = v + (size_t)b * LL * DD + 4 * t;   // this thread's 16B column
    const uint32_t smem0 = (uint32_t)__cvta_generic_to_shared(&buf[0][4 * t]);

    // ---- prologue: issue up to STAGES rows; always commit (empty groups ok) ----
    #pragma unroll
    for (int k = 0; k < STAGES; k++) {
        if (k < n) CP_ASYNC16(smem0 + (uint32_t)k * (DD * 4), gbase + (size_t)(s0 + k) * DD);
        CP_COMMIT();
    }

    float4 mx = make_float4(-CUDART_INF_F, -CUDART_INF_F, -CUDART_INF_F, -CUDART_INF_F);

    // ---- steady state: wait oldest group, consume, issue next, commit ----
    for (int i = 0; i < n; i++) {
        CP_WAIT(STAGES - 1);   // groups are 1/iteration uniform -> row i landed
        const float4 vv = *reinterpret_cast<const float4*>(&buf[i & (STAGES - 1)][4 * t]);
        mx.x = fmaxf(mx.x, vv.x);
        mx.y = fmaxf(mx.y, vv.y);
        mx.z = fmaxf(mx.z, vv.z);
        mx.w = fmaxf(mx.w, vv.w);
        const int nxt = i + STAGES;
        if (nxt < n) CP_ASYNC16(smem0 + (uint32_t)(nxt & (STAGES - 1)) * (DD * 4),
                                gbase + (size_t)(s0 + nxt) * DD);
        CP_COMMIT();
    }

    // Always write (empty chunks write -inf) so the reducer sees valid data.
    reinterpret_cast<float4*>(&g_part[which][b][split][0])[t] = mx;

    // ---- last-arriving CTA for this batch does the final reduce + dot ----
    __threadfence();
    __syncthreads();

    if (t == 0) {
        unsigned int old = atomicAdd(&g_count[b], 1u);
        s_last = (old == 2u * SPLIT - 1u);
    }
    __syncthreads();
    if (!s_last) return;

    __threadfence();   // acquire: see all other CTAs' partials

    float4 fx = make_float4(-CUDART_INF_F, -CUDART_INF_F, -CUDART_INF_F, -CUDART_INF_F);
    float4 fy = fx;
    #pragma unroll 8
    for (int sp = 0; sp < SPLIT; sp++) {
        float4 px = reinterpret_cast<const float4*>(&g_part[0][b][sp][0])[t];
        float4 py = reinterpret_cast<const float4*>(&g_part[1][b][sp][0])[t];
        fx.x = fmaxf(fx.x, px.x); fx.y = fmaxf(fx.y, px.y);
        fx.z = fmaxf(fx.z, px.z); fx.w = fmaxf(fx.w, px.w);
        fy.x = fmaxf(fy.x, py.x); fy.y = fmaxf(fy.y, py.y);
        fy.z = fmaxf(fy.z, py.z); fy.w = fmaxf(fy.w, py.w);
    }

    const float4* W4 = reinterpret_cast<const float4*>(W);
    float4 wx = W4[t];            // W[0:512]    -> x part
    float4 wy = W4[DD / 4 + t];   // W[512:1024] -> y part

    float val = wx.x * fx.x + wx.y * fx.y + wx.z * fx.z + wx.w * fx.w
              + wy.x * fy.x + wy.y * fy.y + wy.z * fy.z + wy.w * fy.w;

    #pragma unroll
    for (int o = 16; o; o >>= 1) val += __shfl_down_sync(0xffffffffu, val, o);

    if ((t & 31) == 0) red[t >> 5] = val;
    __syncthreads();
    if (t == 0) {
        out[b] = red[0] + red[1] + red[2] + red[3] + bias[0];
        g_count[b] = 0;   // reset for the next graph replay
    }
}

extern "C" void kernel_launch(void* const* d_in, const int* in_sizes, int n_in,
                              void* d_out, int out_size)
{
    const float* x      = (const float*)d_in[0];
    const float* y      = (const float*)d_in[1];
    const int*   mask_x = (const int*)d_in[2];
    const int*   mask_y = (const int*)d_in[3];
    const float* W      = (const float*)d_in[4];
    const float* bias   = (const float*)d_in[5];
    float* out          = (float*)d_out;

    fused_kernel<<<dim3(SPLIT, BB, 2), 128>>>(x, y, mask_x, mask_y, W, bias, out);
}